// round 13
// baseline (speedup 1.0000x reference)
#include <cuda_runtime.h>
#include <math.h>

#define NN   1024            // nodes
#define NE   (32 * NN)       // edges
#define CI   8               // in channels
#define NM1  1023
#define PP   (NN * NM1)      // pairs
#define PAIRS_PER_BLK 1024
#define NBLK_PAIRS (PP / PAIRS_PER_BLK)   // 1023

// ---- scratch (device globals; zero-init at load; re-zeroed by k_pairs tail) ----
__device__ float g_deg_out[NN];
__device__ float g_deg_in[NN];
__device__ float g_pfx[NN * CI];   // scaled forward aggregation
__device__ float g_pbx[NN * CI];   // UNSCALED reverse sum (scaled by 1/deg_in in k_node)
__device__ __align__(16) float g_A[NN * 5];   // w1-contribution via out[ii], b1 FOLDED IN
__device__ __align__(16) float g_B[NN * 5];   // w1-contribution via out[jj]

// vectorized global float4 reduction (sm_90+)
__device__ __forceinline__ void red4(float* p, float a, float b, float c, float d) {
    asm volatile("red.global.add.v4.f32 [%0], {%1,%2,%3,%4};"
                 :: "l"(p), "f"(a), "f"(b), "f"(c), "f"(d) : "memory");
}

// ---------------------------------------------------------------- degrees + unscaled Sb
// pbx factorization: reference norm_in = 1/deg_in[ROW], constant per row-segment,
// so pbx[r] = (sum_{e:row=r} x[col_e]) / deg_in[r]. The sum has NO dependency on
// degrees -> accumulate it here; divide in k_node.
__global__ void k_deg(const int* __restrict__ ei, const float* __restrict__ w,
                      const float* __restrict__ x) {
    int e = blockIdx.x * blockDim.x + threadIdx.x;
    if (e >= NE) return;
    int r = ei[e];
    int c = ei[NE + e];
    float we = w[e];
    atomicAdd(&g_deg_out[r], we);
    atomicAdd(&g_deg_in[c], we);
    const float4* xc = (const float4*)(x + c * 8);
    float4 b0 = xc[0], b1 = xc[1];
    red4(&g_pbx[r * 8],     b0.x, b0.y, b0.z, b0.w);
    red4(&g_pbx[r * 8 + 4], b1.x, b1.y, b1.z, b1.w);
}

// ---------------------------------------------------------------- forward aggregation
// pf(x)[col] += x[row]/deg_out[row]   (needs completed deg_out)
__global__ void k_agg(const int* __restrict__ ei, const float* __restrict__ x) {
    int e = blockIdx.x * blockDim.x + threadIdx.x;
    if (e >= NE) return;
    int r = ei[e];
    int c = ei[NE + e];
    float inv_do = __fdividef(1.f, g_deg_out[r]);
    const float4* xr = (const float4*)(x + r * 8);
    float4 a0 = xr[0], a1 = xr[1];
    red4(&g_pfx[c * 8],     inv_do * a0.x, inv_do * a0.y, inv_do * a0.z, inv_do * a0.w);
    red4(&g_pfx[c * 8 + 4], inv_do * a1.x, inv_do * a1.y, inv_do * a1.z, inv_do * a1.w);
}

// ---------------------------------------------------------------- per-node GRU + A/B
// 4 nodes / 128-thread block, grid=256. Weights staged in smem. b1 folded into g_A.
// pbx scaled here: pb = g_pbx * (1/deg_in[n]).
__global__ void __launch_bounds__(128)
k_node(const float* __restrict__ x,
       const float* __restrict__ Wz, const float* __restrict__ bz,
       const float* __restrict__ Wh, const float* __restrict__ bh,
       const float* __restrict__ w1, const float* __restrict__ b1) {
    __shared__ float swz0[8][32], swz1[8][32], swz2[8][32];
    __shared__ float swh0[8][32], swh1[8][32], swh2[8][32];
    __shared__ float sw1s[80][5];
    __shared__ float so[4][33];

    int t = threadIdx.x;
    for (int idx = t; idx < 256; idx += 128) {
        int k = idx >> 5, c = idx & 31, o = k * 32 + c;
        swz0[k][c] = __ldg(Wz + o) + __ldg(Wz + 2560 + o);
        swz1[k][c] = __ldg(Wz + 1280 + o);
        swz2[k][c] = __ldg(Wz + 3840 + o);
        swh0[k][c] = __ldg(Wh + o) + __ldg(Wh + 2560 + o);
        swh1[k][c] = __ldg(Wh + 1280 + o);
        swh2[k][c] = __ldg(Wh + 3840 + o);
    }
    for (int idx = t; idx < 400; idx += 128)
        sw1s[idx / 5][idx % 5] = __ldg(w1 + idx);
    __syncthreads();

    int wid = t >> 5, lane = t & 31;
    int n = blockIdx.x * 4 + wid;
    const int c = lane;

    float inv_di = __fdividef(1.f, g_deg_in[n]);
    float xv[8], pf[8], pb[8];
#pragma unroll
    for (int k = 0; k < 8; k++) {
        xv[k] = __ldg(x + n * 8 + k);
        pf[k] = g_pfx[n * 8 + k];
        pb[k] = g_pbx[n * 8 + k] * inv_di;
    }

    float z = __ldg(bz + c);
    float h = __ldg(bh + c);
#pragma unroll
    for (int k = 0; k < 8; k++) {
        z += xv[k] * swz0[k][c] + pf[k] * swz1[k][c] + pb[k] * swz2[k][c];
        h += xv[k] * swh0[k][c] + pf[k] * swh1[k][c] + pb[k] * swh2[k][c];
    }
    float sig = 1.f / (1.f + __expf(-z));
    float Hn  = (1.f - sig) * tanhf(h);
    so[wid][c] = fmaxf(Hn, 0.f);
    __syncwarp();

    if (lane < 10) {
        int half = lane / 5;           // 0 -> A (w1 rows 0..39), 1 -> B (rows 40..79)
        int m    = lane - half * 5;
        int base = half * 40;
        float acc = (half == 0) ? __ldg(b1 + m) : 0.f;   // fold b1 into A
#pragma unroll
        for (int cc = 0; cc < 32; cc++)
            acc += so[wid][cc] * sw1s[base + cc][m];
#pragma unroll
        for (int k = 0; k < 8; k++)
            acc += xv[k] * sw1s[base + 32 + k][m];
        if (half == 0) g_A[n * 5 + m] = acc;
        else           g_B[n * 5 + m] = acc;
    }
}

// ---------------------------------------------------------------- pair MLP
// 1024 pairs/block, 512 threads x 2 CONSECUTIVE pairs (float2 stream loads,
// float2 store). i0 = kb = b exactly; full g_B table (20KB) staged with float4
// copies. 16 live stream floats -> ~40 regs, no spills.
__global__ void __launch_bounds__(512)
k_pairs(const float* __restrict__ dist, const float* __restrict__ lags,
        const float* __restrict__ lz_,  const float* __restrict__ a2d,
        const float* __restrict__ a2o,  const float* __restrict__ d2a,
        const float* __restrict__ o2a,  const float* __restrict__ vr,
        const float* __restrict__ w1,   const float* __restrict__ w2,
        const float* __restrict__ b2,   const float* __restrict__ w3,
        const float* __restrict__ b3,   const float* __restrict__ w4,
        const float* __restrict__ b4,   float* __restrict__ out) {
    __shared__ float4 sW1[5][3];   // [m]: {wd,wd2,wlg,wz0} {wtd,wto,wda,woa} {wvv,-,-,-}
    __shared__ float4 sW2[3][2];   // [q]: {m0..m3}, {m4, b2q, -, -}
    __shared__ float4 sW3v;        // {w3[0], w3[1], w3[2], b3}
    __shared__ float4 sW4v;        // {w4[0], w4[0]+w4[1], b4, -}
    __shared__ float  sA5[2][5];
    __shared__ __align__(16) float sB[NN * 5];   // full B table (20KB)

    const int b    = blockIdx.x;
    const int pblk = b * PAIRS_PER_BLK;
    const int i0   = b;            // pblk / 1023 == b, pblk % 1023 == b
    int t = threadIdx.x;
    const int p0 = pblk + 2 * t;   // two consecutive pairs

    // ---- issue float2 stream loads immediately (overlap with staging) ----
    float2 v_d  = *(const float2*)(dist + p0);
    float2 v_lg = *(const float2*)(lags + p0);
    float2 v_z0 = *(const float2*)(lz_  + p0);
    float2 v_td = *(const float2*)(a2d  + p0);
    float2 v_to = *(const float2*)(a2o  + p0);
    float2 v_da = *(const float2*)(d2a  + p0);
    float2 v_oa = *(const float2*)(o2a  + p0);
    float2 v_vv = *(const float2*)(vr   + p0);

    // tail-zero scratch for next launch (dead by this point): 18432 floats
    {
        int zi = b * 512 + t;
        if (zi < NN / 2) ((float2*)g_deg_out)[zi] = make_float2(0.f, 0.f);
        else if (zi < NN) ((float2*)g_deg_in)[zi - NN / 2] = make_float2(0.f, 0.f);
        else if (zi < NN + NN * CI / 4)
            ((float4*)g_pfx)[zi - NN] = make_float4(0.f, 0.f, 0.f, 0.f);
        else if (zi < NN + NN * CI / 2)
            ((float4*)g_pbx)[zi - NN - NN * CI / 4] = make_float4(0.f, 0.f, 0.f, 0.f);
    }

    // stage packed weights
    if (t < 15) {                              // sW1: m = t/3, part = t%3
        int m = t / 3, part = t - m * 3;
        int f = part * 4;
        float a0 = w1[400 + f * 5 + m];
        float a1 = (part < 2) ? w1[400 + (f + 1) * 5 + m] : 0.f;
        float a2 = (part < 2) ? w1[400 + (f + 2) * 5 + m] : 0.f;
        float a3 = (part < 2) ? w1[400 + (f + 3) * 5 + m] : 0.f;
        sW1[m][part] = make_float4(a0, a1, a2, a3);
    } else if (t < 21) {                       // sW2: q = (t-15)/2, part = (t-15)%2
        int idx = t - 15, q = idx / 2, part = idx - q * 2;
        if (part == 0)
            sW2[q][0] = make_float4(w2[0 * 3 + q], w2[1 * 3 + q], w2[2 * 3 + q], w2[3 * 3 + q]);
        else
            sW2[q][1] = make_float4(w2[4 * 3 + q], b2[q], 0.f, 0.f);
    } else if (t == 21) {
        sW3v = make_float4(w3[0], w3[1], w3[2], b3[0]);
    } else if (t == 22) {
        float a = w4[0];
        sW4v = make_float4(a, a + w4[1], b4[0], 0.f);
    } else if (t >= 32 && t < 42) {            // stage A rows i0, i0+1 (b1 folded in)
        int q = t - 32, ia = q / 5, m = q - ia * 5;
        sA5[ia][m] = g_A[(i0 + ia) * 5 + m];   // i0+1 <= 1023, in range
    }
    // stage FULL B table: 5120 floats = 1280 float4, pure vector copy
#pragma unroll
    for (int idx = t; idx < 1280; idx += 512)
        ((float4*)sB)[idx] = ((const float4*)g_B)[idx];
    __syncthreads();

    float dS[2]  = {v_d.x,  v_d.y};
    float lgS[2] = {v_lg.x, v_lg.y};
    float z0S[2] = {v_z0.x, v_z0.y};
    float tdS[2] = {v_td.x, v_td.y};
    float toS[2] = {v_to.x, v_to.y};
    float daS[2] = {v_da.x, v_da.y};
    float oaS[2] = {v_oa.x, v_oa.y};
    float vvS[2] = {v_vv.x, v_vv.y};

    float y[2];
#pragma unroll
    for (int r = 0; r < 2; r++) {
        // i, k for this pair: k0 = b + 2t + r, at most one wrap (k0 <= b+1023 < 2046)
        int k = b + 2 * t + r;                 // kb == i0 == b
        int i = i0;
        if (k >= NM1) { k -= NM1; ++i; }
        int j = (k < i) ? k : (k + 1);

        const float* Bp = sB + j * 5;
        const float* Ap = sA5[i - i0];
        float d = dS[r], d2 = d * d;

        float h1[5];
#pragma unroll
        for (int m = 0; m < 5; m++) {
            float4 wa = sW1[m][0], wb = sW1[m][1], wc = sW1[m][2];
            float v = Ap[m] + Bp[m];
            v += d      * wa.x + d2     * wa.y + lgS[r] * wa.z + z0S[r] * wa.w;
            v += tdS[r] * wb.x + toS[r] * wb.y + daS[r] * wb.z + oaS[r] * wb.w;
            v += vvS[r] * wc.x;
            h1[m] = fmaxf(v, 0.f);
        }
        float h2[3];
#pragma unroll
        for (int q = 0; q < 3; q++) {
            float4 u = sW2[q][0], u2 = sW2[q][1];
            float v = u2.y + h1[0] * u.x + h1[1] * u.y + h1[2] * u.z + h1[3] * u.w + h1[4] * u2.x;
            h2[q] = fmaxf(v, 0.f);
        }
        float4 w3v = sW3v;
        float h3 = w3v.w + h2[0] * w3v.x + h2[1] * w3v.y + h2[2] * w3v.z;
        float4 w4v = sW4v;
        // lag_zeros is exactly 0.0 or 1.0 (round of uniform)
        float w4eff = (z0S[r] != 0.f) ? w4v.y : w4v.x;
        y[r] = h3 * w4eff + w4v.z;
    }
    *(float2*)(out + p0) = make_float2(y[0], y[1]);
}

// ---------------------------------------------------------------- launch
extern "C" void kernel_launch(void* const* d_in, const int* in_sizes, int n_in,
                              void* d_out, int out_size) {
    const float* x    = (const float*)d_in[0];
    const int*   ei   = (const int*)  d_in[1];
    const float* ew   = (const float*)d_in[2];
    const float* dist = (const float*)d_in[3];
    const float* lags = (const float*)d_in[4];
    const float* lz   = (const float*)d_in[5];
    const float* a2d  = (const float*)d_in[6];
    const float* a2o  = (const float*)d_in[7];
    const float* d2a  = (const float*)d_in[8];
    const float* o2a  = (const float*)d_in[9];
    const float* vr   = (const float*)d_in[10];
    const float* Wz   = (const float*)d_in[11];
    const float* bz   = (const float*)d_in[12];
    // d_in[13], d_in[14] = Wr, br — dead (H0 == 0 makes the reset gate a no-op)
    const float* Wh   = (const float*)d_in[15];
    const float* bh   = (const float*)d_in[16];
    const float* w1   = (const float*)d_in[17];
    const float* b1   = (const float*)d_in[18];
    const float* w2   = (const float*)d_in[19];
    const float* b2   = (const float*)d_in[20];
    const float* w3   = (const float*)d_in[21];
    const float* b3   = (const float*)d_in[22];
    const float* w4   = (const float*)d_in[23];
    const float* b4   = (const float*)d_in[24];
    float* out = (float*)d_out;

    k_deg<<<(NE + 255) / 256, 256>>>(ei, ew, x);
    k_agg<<<(NE + 255) / 256, 256>>>(ei, x);
    k_node<<<NN / 4, 128>>>(x, Wz, bz, Wh, bh, w1, b1);
    k_pairs<<<NBLK_PAIRS, 512>>>(dist, lags, lz, a2d, a2o, d2a, o2a, vr,
                                 w1, w2, b2, w3, b3, w4, b4, out);
}

// round 15
// speedup vs baseline: 1.0804x; 1.0804x over previous
#include <cuda_runtime.h>
#include <math.h>

#define NN   1024            // nodes
#define NE   (32 * NN)       // edges
#define CI   8               // in channels
#define NM1  1023
#define PP   (NN * NM1)      // pairs
#define PAIRS_PER_BLK 1024
#define NBLK_PAIRS (PP / PAIRS_PER_BLK)   // 1023

// ---- scratch (device globals; zero-init at load; re-zeroed by k_pairs tail) ----
__device__ float g_deg_out[NN];
__device__ float g_deg_in[NN];
__device__ float g_pfx[NN * CI];   // scaled forward aggregation
__device__ float g_pbx[NN * CI];   // UNSCALED reverse sum (scaled by 1/deg_in in k_node)
__device__ __align__(16) float g_A[NN * 5];   // w1-contribution via out[ii], b1 FOLDED IN
__device__ __align__(16) float g_B[NN * 5];   // w1-contribution via out[jj]

// vectorized global float4 reduction (sm_90+)
__device__ __forceinline__ void red4(float* p, float a, float b, float c, float d) {
    asm volatile("red.global.add.v4.f32 [%0], {%1,%2,%3,%4};"
                 :: "l"(p), "f"(a), "f"(b), "f"(c), "f"(d) : "memory");
}

// ---------------------------------------------------------------- degrees + unscaled Sb
// pbx factorization: reference norm_in = 1/deg_in[ROW], constant per row-segment,
// so pbx[r] = (sum_{e:row=r} x[col_e]) / deg_in[r]. The sum has NO dependency on
// degrees -> accumulate it here; divide in k_node.
__global__ void k_deg(const int* __restrict__ ei, const float* __restrict__ w,
                      const float* __restrict__ x) {
    int e = blockIdx.x * blockDim.x + threadIdx.x;
    if (e >= NE) return;
    int r = ei[e];
    int c = ei[NE + e];
    float we = w[e];
    atomicAdd(&g_deg_out[r], we);
    atomicAdd(&g_deg_in[c], we);
    const float4* xc = (const float4*)(x + c * 8);
    float4 b0 = xc[0], b1 = xc[1];
    red4(&g_pbx[r * 8],     b0.x, b0.y, b0.z, b0.w);
    red4(&g_pbx[r * 8 + 4], b1.x, b1.y, b1.z, b1.w);
}

// ---------------------------------------------------------------- forward aggregation
// pf(x)[col] += x[row]/deg_out[row]   (needs completed deg_out)
__global__ void k_agg(const int* __restrict__ ei, const float* __restrict__ x) {
    int e = blockIdx.x * blockDim.x + threadIdx.x;
    if (e >= NE) return;
    int r = ei[e];
    int c = ei[NE + e];
    float inv_do = __fdividef(1.f, g_deg_out[r]);
    const float4* xr = (const float4*)(x + r * 8);
    float4 a0 = xr[0], a1 = xr[1];
    red4(&g_pfx[c * 8],     inv_do * a0.x, inv_do * a0.y, inv_do * a0.z, inv_do * a0.w);
    red4(&g_pfx[c * 8 + 4], inv_do * a1.x, inv_do * a1.y, inv_do * a1.z, inv_do * a1.w);
}

// ---------------------------------------------------------------- per-node GRU + A/B
// 4 nodes / 128-thread block, grid=256. Weights staged in smem. b1 folded into g_A.
// pbx scaled here: pb = g_pbx * (1/deg_in[n]).
__global__ void __launch_bounds__(128)
k_node(const float* __restrict__ x,
       const float* __restrict__ Wz, const float* __restrict__ bz,
       const float* __restrict__ Wh, const float* __restrict__ bh,
       const float* __restrict__ w1, const float* __restrict__ b1) {
    __shared__ float swz0[8][32], swz1[8][32], swz2[8][32];
    __shared__ float swh0[8][32], swh1[8][32], swh2[8][32];
    __shared__ float sw1s[80][5];
    __shared__ float so[4][33];

    int t = threadIdx.x;
    for (int idx = t; idx < 256; idx += 128) {
        int k = idx >> 5, c = idx & 31, o = k * 32 + c;
        swz0[k][c] = __ldg(Wz + o) + __ldg(Wz + 2560 + o);
        swz1[k][c] = __ldg(Wz + 1280 + o);
        swz2[k][c] = __ldg(Wz + 3840 + o);
        swh0[k][c] = __ldg(Wh + o) + __ldg(Wh + 2560 + o);
        swh1[k][c] = __ldg(Wh + 1280 + o);
        swh2[k][c] = __ldg(Wh + 3840 + o);
    }
    for (int idx = t; idx < 400; idx += 128)
        sw1s[idx / 5][idx % 5] = __ldg(w1 + idx);
    __syncthreads();

    int wid = t >> 5, lane = t & 31;
    int n = blockIdx.x * 4 + wid;
    const int c = lane;

    float inv_di = __fdividef(1.f, g_deg_in[n]);
    float xv[8], pf[8], pb[8];
#pragma unroll
    for (int k = 0; k < 8; k++) {
        xv[k] = __ldg(x + n * 8 + k);
        pf[k] = g_pfx[n * 8 + k];
        pb[k] = g_pbx[n * 8 + k] * inv_di;
    }

    float z = __ldg(bz + c);
    float h = __ldg(bh + c);
#pragma unroll
    for (int k = 0; k < 8; k++) {
        z += xv[k] * swz0[k][c] + pf[k] * swz1[k][c] + pb[k] * swz2[k][c];
        h += xv[k] * swh0[k][c] + pf[k] * swh1[k][c] + pb[k] * swh2[k][c];
    }
    float sig = 1.f / (1.f + __expf(-z));
    float Hn  = (1.f - sig) * tanhf(h);
    so[wid][c] = fmaxf(Hn, 0.f);
    __syncwarp();

    if (lane < 10) {
        int half = lane / 5;           // 0 -> A (w1 rows 0..39), 1 -> B (rows 40..79)
        int m    = lane - half * 5;
        int base = half * 40;
        float acc = (half == 0) ? __ldg(b1 + m) : 0.f;   // fold b1 into A
#pragma unroll
        for (int cc = 0; cc < 32; cc++)
            acc += so[wid][cc] * sw1s[base + cc][m];
#pragma unroll
        for (int k = 0; k < 8; k++)
            acc += xv[k] * sw1s[base + 32 + k][m];
        if (half == 0) g_A[n * 5 + m] = acc;
        else           g_B[n * 5 + m] = acc;
    }
}

// ---------------------------------------------------------------- pair MLP
// 1024 pairs/block (512 threads x 2, stride 512 — j is thread-consecutive, so
// sB reads are conflict-free). Full g_B table (20KB) staged with float4 copies.
__global__ void __launch_bounds__(512)
k_pairs(const float* __restrict__ dist, const float* __restrict__ lags,
        const float* __restrict__ lz_,  const float* __restrict__ a2d,
        const float* __restrict__ a2o,  const float* __restrict__ d2a,
        const float* __restrict__ o2a,  const float* __restrict__ vr,
        const float* __restrict__ w1,   const float* __restrict__ w2,
        const float* __restrict__ b2,   const float* __restrict__ w3,
        const float* __restrict__ b3,   const float* __restrict__ w4,
        const float* __restrict__ b4,   float* __restrict__ out) {
    __shared__ float4 sW1[5][3];   // [m]: {wd,wd2,wlg,wz0} {wtd,wto,wda,woa} {wvv,-,-,-}
    __shared__ float4 sW2[3][2];   // [q]: {m0..m3}, {m4, b2q, -, -}
    __shared__ float4 sW3v;        // {w3[0], w3[1], w3[2], b3}
    __shared__ float4 sW4v;        // {w4[0], w4[0]+w4[1], b4, -}
    __shared__ float  sA5[2][5];
    __shared__ __align__(16) float sB[NN * 5];   // full B table (20KB)

    const int b   = blockIdx.x;
    const int pblk = b * PAIRS_PER_BLK;
    const int i0  = b;             // pblk / 1023 == b, pblk % 1023 == b
    int t = threadIdx.x;
    const int p0 = pblk + t;

    // ---- issue stream loads for BOTH pairs immediately (MLP=16) ----
    float dS[2], lgS[2], z0S[2], tdS[2], toS[2], daS[2], oaS[2], vvS[2];
#pragma unroll
    for (int r = 0; r < 2; r++) {
        int p = p0 + r * 512;
        dS[r]  = __ldg(dist + p);
        lgS[r] = __ldg(lags + p);
        z0S[r] = __ldg(lz_  + p);
        tdS[r] = __ldg(a2d  + p);
        toS[r] = __ldg(a2o  + p);
        daS[r] = __ldg(d2a  + p);
        oaS[r] = __ldg(o2a  + p);
        vvS[r] = __ldg(vr   + p);
    }

    // tail-zero scratch for next launch (dead by this point): 18432 floats
    {
        int zi = b * 512 + t;
        if (zi < NN / 2) ((float2*)g_deg_out)[zi] = make_float2(0.f, 0.f);
        else if (zi < NN) ((float2*)g_deg_in)[zi - NN / 2] = make_float2(0.f, 0.f);
        else if (zi < NN + NN * CI / 4)
            ((float4*)g_pfx)[zi - NN] = make_float4(0.f, 0.f, 0.f, 0.f);
        else if (zi < NN + NN * CI / 2)
            ((float4*)g_pbx)[zi - NN - NN * CI / 4] = make_float4(0.f, 0.f, 0.f, 0.f);
    }

    // stage packed weights
    if (t < 15) {                              // sW1: m = t/3, part = t%3
        int m = t / 3, part = t - m * 3;
        int f = part * 4;
        float a0 = w1[400 + f * 5 + m];
        float a1 = (part < 2) ? w1[400 + (f + 1) * 5 + m] : 0.f;
        float a2 = (part < 2) ? w1[400 + (f + 2) * 5 + m] : 0.f;
        float a3 = (part < 2) ? w1[400 + (f + 3) * 5 + m] : 0.f;
        sW1[m][part] = make_float4(a0, a1, a2, a3);
    } else if (t < 21) {                       // sW2: q = (t-15)/2, part = (t-15)%2
        int idx = t - 15, q = idx / 2, part = idx - q * 2;
        if (part == 0)
            sW2[q][0] = make_float4(w2[0 * 3 + q], w2[1 * 3 + q], w2[2 * 3 + q], w2[3 * 3 + q]);
        else
            sW2[q][1] = make_float4(w2[4 * 3 + q], b2[q], 0.f, 0.f);
    } else if (t == 21) {
        sW3v = make_float4(w3[0], w3[1], w3[2], b3[0]);
    } else if (t == 22) {
        float a = w4[0];
        sW4v = make_float4(a, a + w4[1], b4[0], 0.f);
    } else if (t >= 32 && t < 42) {            // stage A rows i0, i0+1 (b1 folded in)
        int q = t - 32, ia = q / 5, m = q - ia * 5;
        sA5[ia][m] = g_A[(i0 + ia) * 5 + m];   // i0+1 <= 1023, in range
    }
    // stage FULL B table: 5120 floats = 1280 float4, pure vector copy
#pragma unroll
    for (int idx = t; idx < 1280; idx += 512)
        ((float4*)sB)[idx] = ((const float4*)g_B)[idx];
    __syncthreads();

#pragma unroll
    for (int r = 0; r < 2; r++) {
        // i, k for this pair (exactly one wrap across the block's k-range)
        int k = b + t + r * 512;
        int i = i0;
        if (k >= NM1) { k -= NM1; i = i0 + 1; }
        int j = (k < i) ? k : (k + 1);

        const float* Bp = sB + j * 5;
        const float* Ap = sA5[i - i0];
        float d = dS[r], d2 = d * d;

        float h1[5];
#pragma unroll
        for (int m = 0; m < 5; m++) {
            float4 wa = sW1[m][0], wb = sW1[m][1], wc = sW1[m][2];
            float v = Ap[m] + Bp[m];
            v += d      * wa.x + d2     * wa.y + lgS[r] * wa.z + z0S[r] * wa.w;
            v += tdS[r] * wb.x + toS[r] * wb.y + daS[r] * wb.z + oaS[r] * wb.w;
            v += vvS[r] * wc.x;
            h1[m] = fmaxf(v, 0.f);
        }
        float h2[3];
#pragma unroll
        for (int q = 0; q < 3; q++) {
            float4 u = sW2[q][0], u2 = sW2[q][1];
            float v = u2.y + h1[0] * u.x + h1[1] * u.y + h1[2] * u.z + h1[3] * u.w + h1[4] * u2.x;
            h2[q] = fmaxf(v, 0.f);
        }
        float4 w3v = sW3v;
        float h3 = w3v.w + h2[0] * w3v.x + h2[1] * w3v.y + h2[2] * w3v.z;
        float4 w4v = sW4v;
        // lag_zeros is exactly 0.0 or 1.0 (round of uniform)
        float w4eff = (z0S[r] != 0.f) ? w4v.y : w4v.x;
        out[p0 + r * 512] = h3 * w4eff + w4v.z;
    }
}

// ---------------------------------------------------------------- launch
extern "C" void kernel_launch(void* const* d_in, const int* in_sizes, int n_in,
                              void* d_out, int out_size) {
    const float* x    = (const float*)d_in[0];
    const int*   ei   = (const int*)  d_in[1];
    const float* ew   = (const float*)d_in[2];
    const float* dist = (const float*)d_in[3];
    const float* lags = (const float*)d_in[4];
    const float* lz   = (const float*)d_in[5];
    const float* a2d  = (const float*)d_in[6];
    const float* a2o  = (const float*)d_in[7];
    const float* d2a  = (const float*)d_in[8];
    const float* o2a  = (const float*)d_in[9];
    const float* vr   = (const float*)d_in[10];
    const float* Wz   = (const float*)d_in[11];
    const float* bz   = (const float*)d_in[12];
    // d_in[13], d_in[14] = Wr, br — dead (H0 == 0 makes the reset gate a no-op)
    const float* Wh   = (const float*)d_in[15];
    const float* bh   = (const float*)d_in[16];
    const float* w1   = (const float*)d_in[17];
    const float* b1   = (const float*)d_in[18];
    const float* w2   = (const float*)d_in[19];
    const float* b2   = (const float*)d_in[20];
    const float* w3   = (const float*)d_in[21];
    const float* b3   = (const float*)d_in[22];
    const float* w4   = (const float*)d_in[23];
    const float* b4   = (const float*)d_in[24];
    float* out = (float*)d_out;

    k_deg<<<(NE + 255) / 256, 256>>>(ei, ew, x);
    k_agg<<<(NE + 255) / 256, 256>>>(ei, x);
    k_node<<<NN / 4, 128>>>(x, Wz, bz, Wh, bh, w1, b1);
    k_pairs<<<NBLK_PAIRS, 512>>>(dist, lags, lz, a2d, a2o, d2a, o2a, vr,
                                 w1, w2, b2, w3, b3, w4, b4, out);
}

// round 16
// speedup vs baseline: 1.0832x; 1.0026x over previous
#include <cuda_runtime.h>
#include <math.h>

#define NN   1024            // nodes
#define NE   (32 * NN)       // edges
#define CI   8               // in channels
#define NM1  1023
#define PP   (NN * NM1)      // pairs
#define PAIRS_PER_BLK 1024
#define NTILES 1023          // PP / PAIRS_PER_BLK
#define GRID_PAIRS 444       // 148 SMs x 3 co-resident -> single wave, persistent

// ---- scratch (device globals; zero-init at load; re-zeroed by k_pairs tail) ----
__device__ float g_deg_out[NN];
__device__ float g_deg_in[NN];
__device__ float g_pfx[NN * CI];   // scaled forward aggregation
__device__ float g_pbx[NN * CI];   // UNSCALED reverse sum (scaled by 1/deg_in in k_node)
__device__ __align__(16) float g_A[NN * 5];   // w1-contribution via out[ii], b1 FOLDED IN
__device__ __align__(16) float g_B[NN * 5];   // w1-contribution via out[jj]

// vectorized global float4 reduction (sm_90+)
__device__ __forceinline__ void red4(float* p, float a, float b, float c, float d) {
    asm volatile("red.global.add.v4.f32 [%0], {%1,%2,%3,%4};"
                 :: "l"(p), "f"(a), "f"(b), "f"(c), "f"(d) : "memory");
}

// ---------------------------------------------------------------- degrees + unscaled Sb
// pbx factorization: reference norm_in = 1/deg_in[ROW], constant per row-segment,
// so pbx[r] = (sum_{e:row=r} x[col_e]) / deg_in[r]. The sum has NO dependency on
// degrees -> accumulate it here; divide in k_node.
__global__ void k_deg(const int* __restrict__ ei, const float* __restrict__ w,
                      const float* __restrict__ x) {
    int e = blockIdx.x * blockDim.x + threadIdx.x;
    if (e >= NE) return;
    int r = ei[e];
    int c = ei[NE + e];
    float we = w[e];
    atomicAdd(&g_deg_out[r], we);
    atomicAdd(&g_deg_in[c], we);
    const float4* xc = (const float4*)(x + c * 8);
    float4 b0 = xc[0], b1 = xc[1];
    red4(&g_pbx[r * 8],     b0.x, b0.y, b0.z, b0.w);
    red4(&g_pbx[r * 8 + 4], b1.x, b1.y, b1.z, b1.w);
}

// ---------------------------------------------------------------- forward aggregation
// pf(x)[col] += x[row]/deg_out[row]   (needs completed deg_out)
__global__ void k_agg(const int* __restrict__ ei, const float* __restrict__ x) {
    int e = blockIdx.x * blockDim.x + threadIdx.x;
    if (e >= NE) return;
    int r = ei[e];
    int c = ei[NE + e];
    float inv_do = __fdividef(1.f, g_deg_out[r]);
    const float4* xr = (const float4*)(x + r * 8);
    float4 a0 = xr[0], a1 = xr[1];
    red4(&g_pfx[c * 8],     inv_do * a0.x, inv_do * a0.y, inv_do * a0.z, inv_do * a0.w);
    red4(&g_pfx[c * 8 + 4], inv_do * a1.x, inv_do * a1.y, inv_do * a1.z, inv_do * a1.w);
}

// ---------------------------------------------------------------- per-node GRU + A/B
// 4 nodes / 128-thread block, grid=256. Weights staged in smem. b1 folded into g_A.
// pbx scaled here: pb = g_pbx * (1/deg_in[n]).
__global__ void __launch_bounds__(128)
k_node(const float* __restrict__ x,
       const float* __restrict__ Wz, const float* __restrict__ bz,
       const float* __restrict__ Wh, const float* __restrict__ bh,
       const float* __restrict__ w1, const float* __restrict__ b1) {
    __shared__ float swz0[8][32], swz1[8][32], swz2[8][32];
    __shared__ float swh0[8][32], swh1[8][32], swh2[8][32];
    __shared__ float sw1s[80][5];
    __shared__ float so[4][33];

    int t = threadIdx.x;
    for (int idx = t; idx < 256; idx += 128) {
        int k = idx >> 5, c = idx & 31, o = k * 32 + c;
        swz0[k][c] = __ldg(Wz + o) + __ldg(Wz + 2560 + o);
        swz1[k][c] = __ldg(Wz + 1280 + o);
        swz2[k][c] = __ldg(Wz + 3840 + o);
        swh0[k][c] = __ldg(Wh + o) + __ldg(Wh + 2560 + o);
        swh1[k][c] = __ldg(Wh + 1280 + o);
        swh2[k][c] = __ldg(Wh + 3840 + o);
    }
    for (int idx = t; idx < 400; idx += 128)
        sw1s[idx / 5][idx % 5] = __ldg(w1 + idx);
    __syncthreads();

    int wid = t >> 5, lane = t & 31;
    int n = blockIdx.x * 4 + wid;
    const int c = lane;

    float inv_di = __fdividef(1.f, g_deg_in[n]);
    float xv[8], pf[8], pb[8];
#pragma unroll
    for (int k = 0; k < 8; k++) {
        xv[k] = __ldg(x + n * 8 + k);
        pf[k] = g_pfx[n * 8 + k];
        pb[k] = g_pbx[n * 8 + k] * inv_di;
    }

    float z = __ldg(bz + c);
    float h = __ldg(bh + c);
#pragma unroll
    for (int k = 0; k < 8; k++) {
        z += xv[k] * swz0[k][c] + pf[k] * swz1[k][c] + pb[k] * swz2[k][c];
        h += xv[k] * swh0[k][c] + pf[k] * swh1[k][c] + pb[k] * swh2[k][c];
    }
    float sig = 1.f / (1.f + __expf(-z));
    float Hn  = (1.f - sig) * tanhf(h);
    so[wid][c] = fmaxf(Hn, 0.f);
    __syncwarp();

    if (lane < 10) {
        int half = lane / 5;           // 0 -> A (w1 rows 0..39), 1 -> B (rows 40..79)
        int m    = lane - half * 5;
        int base = half * 40;
        float acc = (half == 0) ? __ldg(b1 + m) : 0.f;   // fold b1 into A
#pragma unroll
        for (int cc = 0; cc < 32; cc++)
            acc += so[wid][cc] * sw1s[base + cc][m];
#pragma unroll
        for (int k = 0; k < 8; k++)
            acc += xv[k] * sw1s[base + 32 + k][m];
        if (half == 0) g_A[n * 5 + m] = acc;
        else           g_B[n * 5 + m] = acc;
    }
}

// ---------------------------------------------------------------- pair MLP (persistent)
// 444 blocks x 512 threads, single co-resident wave. Each block stages the full
// g_B table (20KB) + packed weights ONCE, then loops over tiles of 1024 pairs
// (tile = bb, bb+444, ...). Per tile: i0 = kb = tile; stride-512 two-pair
// mapping (j thread-consecutive -> conflict-free sB); A rows read via
// warp-uniform __ldg (broadcast, L1-hit) so no per-tile barrier.
__global__ void __launch_bounds__(512)
k_pairs(const float* __restrict__ dist, const float* __restrict__ lags,
        const float* __restrict__ lz_,  const float* __restrict__ a2d,
        const float* __restrict__ a2o,  const float* __restrict__ d2a,
        const float* __restrict__ o2a,  const float* __restrict__ vr,
        const float* __restrict__ w1,   const float* __restrict__ w2,
        const float* __restrict__ b2,   const float* __restrict__ w3,
        const float* __restrict__ b3,   const float* __restrict__ w4,
        const float* __restrict__ b4,   float* __restrict__ out) {
    __shared__ float4 sW1[5][3];   // [m]: {wd,wd2,wlg,wz0} {wtd,wto,wda,woa} {wvv,-,-,-}
    __shared__ float4 sW2[3][2];   // [q]: {m0..m3}, {m4, b2q, -, -}
    __shared__ float4 sW3v;        // {w3[0], w3[1], w3[2], b3}
    __shared__ float4 sW4v;        // {w4[0], w4[0]+w4[1], b4, -}
    __shared__ __align__(16) float sB[NN * 5];   // full B table (20KB)

    const int bb = blockIdx.x;
    int t = threadIdx.x;

    // tail-zero scratch for next launch (dead by this point): 18432 floats
    {
        int zi = bb * 512 + t;
        if (zi < NN / 2) ((float2*)g_deg_out)[zi] = make_float2(0.f, 0.f);
        else if (zi < NN) ((float2*)g_deg_in)[zi - NN / 2] = make_float2(0.f, 0.f);
        else if (zi < NN + NN * CI / 4)
            ((float4*)g_pfx)[zi - NN] = make_float4(0.f, 0.f, 0.f, 0.f);
        else if (zi < NN + NN * CI / 2)
            ((float4*)g_pbx)[zi - NN - NN * CI / 4] = make_float4(0.f, 0.f, 0.f, 0.f);
    }

    // stage packed weights (once per block)
    if (t < 15) {                              // sW1: m = t/3, part = t%3
        int m = t / 3, part = t - m * 3;
        int f = part * 4;
        float a0 = w1[400 + f * 5 + m];
        float a1 = (part < 2) ? w1[400 + (f + 1) * 5 + m] : 0.f;
        float a2 = (part < 2) ? w1[400 + (f + 2) * 5 + m] : 0.f;
        float a3 = (part < 2) ? w1[400 + (f + 3) * 5 + m] : 0.f;
        sW1[m][part] = make_float4(a0, a1, a2, a3);
    } else if (t < 21) {                       // sW2: q = (t-15)/2, part = (t-15)%2
        int idx = t - 15, q = idx / 2, part = idx - q * 2;
        if (part == 0)
            sW2[q][0] = make_float4(w2[0 * 3 + q], w2[1 * 3 + q], w2[2 * 3 + q], w2[3 * 3 + q]);
        else
            sW2[q][1] = make_float4(w2[4 * 3 + q], b2[q], 0.f, 0.f);
    } else if (t == 21) {
        sW3v = make_float4(w3[0], w3[1], w3[2], b3[0]);
    } else if (t == 22) {
        float a = w4[0];
        sW4v = make_float4(a, a + w4[1], b4[0], 0.f);
    }
    // stage FULL B table once: 5120 floats = 1280 float4
#pragma unroll
    for (int idx = t; idx < 1280; idx += 512)
        ((float4*)sB)[idx] = ((const float4*)g_B)[idx];
    __syncthreads();

    // persistent tile loop
    for (int tile = bb; tile < NTILES; tile += GRID_PAIRS) {
        const int pblk = tile * PAIRS_PER_BLK;
        const int i0   = tile;                 // pblk/1023 == tile, pblk%1023 == tile
        const int p0   = pblk + t;

        float dS[2], lgS[2], z0S[2], tdS[2], toS[2], daS[2], oaS[2], vvS[2];
#pragma unroll
        for (int r = 0; r < 2; r++) {
            int p = p0 + r * 512;
            dS[r]  = __ldg(dist + p);
            lgS[r] = __ldg(lags + p);
            z0S[r] = __ldg(lz_  + p);
            tdS[r] = __ldg(a2d  + p);
            toS[r] = __ldg(a2o  + p);
            daS[r] = __ldg(d2a  + p);
            oaS[r] = __ldg(o2a  + p);
            vvS[r] = __ldg(vr   + p);
        }

#pragma unroll
        for (int r = 0; r < 2; r++) {
            // i, k for this pair (exactly one wrap across the tile's k-range)
            int k = tile + t + r * 512;
            int i = i0;
            if (k >= NM1) { k -= NM1; i = i0 + 1; }
            int j = (k < i) ? k : (k + 1);

            const float* Bp = sB + j * 5;
            const float* Ap = g_A + i * 5;     // warp-uniform -> broadcast LDG, L1-hit
            float d = dS[r], d2 = d * d;

            float h1[5];
#pragma unroll
            for (int m = 0; m < 5; m++) {
                float4 wa = sW1[m][0], wb = sW1[m][1], wc = sW1[m][2];
                float v = __ldg(Ap + m) + Bp[m];
                v += d      * wa.x + d2     * wa.y + lgS[r] * wa.z + z0S[r] * wa.w;
                v += tdS[r] * wb.x + toS[r] * wb.y + daS[r] * wb.z + oaS[r] * wb.w;
                v += vvS[r] * wc.x;
                h1[m] = fmaxf(v, 0.f);
            }
            float h2[3];
#pragma unroll
            for (int q = 0; q < 3; q++) {
                float4 u = sW2[q][0], u2 = sW2[q][1];
                float v = u2.y + h1[0] * u.x + h1[1] * u.y + h1[2] * u.z + h1[3] * u.w + h1[4] * u2.x;
                h2[q] = fmaxf(v, 0.f);
            }
            float4 w3v = sW3v;
            float h3 = w3v.w + h2[0] * w3v.x + h2[1] * w3v.y + h2[2] * w3v.z;
            float4 w4v = sW4v;
            // lag_zeros is exactly 0.0 or 1.0 (round of uniform)
            float w4eff = (z0S[r] != 0.f) ? w4v.y : w4v.x;
            out[p0 + r * 512] = h3 * w4eff + w4v.z;
        }
    }
}

// ---------------------------------------------------------------- launch
extern "C" void kernel_launch(void* const* d_in, const int* in_sizes, int n_in,
                              void* d_out, int out_size) {
    const float* x    = (const float*)d_in[0];
    const int*   ei   = (const int*)  d_in[1];
    const float* ew   = (const float*)d_in[2];
    const float* dist = (const float*)d_in[3];
    const float* lags = (const float*)d_in[4];
    const float* lz   = (const float*)d_in[5];
    const float* a2d  = (const float*)d_in[6];
    const float* a2o  = (const float*)d_in[7];
    const float* d2a  = (const float*)d_in[8];
    const float* o2a  = (const float*)d_in[9];
    const float* vr   = (const float*)d_in[10];
    const float* Wz   = (const float*)d_in[11];
    const float* bz   = (const float*)d_in[12];
    // d_in[13], d_in[14] = Wr, br — dead (H0 == 0 makes the reset gate a no-op)
    const float* Wh   = (const float*)d_in[15];
    const float* bh   = (const float*)d_in[16];
    const float* w1   = (const float*)d_in[17];
    const float* b1   = (const float*)d_in[18];
    const float* w2   = (const float*)d_in[19];
    const float* b2   = (const float*)d_in[20];
    const float* w3   = (const float*)d_in[21];
    const float* b3   = (const float*)d_in[22];
    const float* w4   = (const float*)d_in[23];
    const float* b4   = (const float*)d_in[24];
    float* out = (float*)d_out;

    k_deg<<<(NE + 255) / 256, 256>>>(ei, ew, x);
    k_agg<<<(NE + 255) / 256, 256>>>(ei, x);
    k_node<<<NN / 4, 128>>>(x, Wz, bz, Wh, bh, w1, b1);
    k_pairs<<<GRID_PAIRS, 512>>>(dist, lags, lz, a2d, a2o, d2a, o2a, vr,
                                 w1, w2, b2, w3, b3, w4, b4, out);
}